// round 16
// baseline (speedup 1.0000x reference)
#include <cuda_runtime.h>
#include <cuda_fp16.h>
#include <math.h>
#include <stdint.h>

#define NN      16384
#define BG      64
#define H       256
#define NHEADS  8
#define HD      32

// ======================= scratch (device globals) ===========================
__device__ __half g_xn [NN * H];
__device__ __half g_qkv[NN * 3 * H];
__device__ __half g_ctx[NN * H];
__device__ float  g_xmid[NN * H];
__device__ __half g_xn2[NN * H];
__device__ __half g_hid[NN * 4 * H];
__device__ __half g_wqkv[3 * H * H];
__device__ __half g_wout[H * H];
__device__ __half g_w1[4 * H * H];
__device__ __half g_w2[H * 4 * H];
__device__ int g_counts[BG];
__device__ int g_starts[BG];

__device__ __forceinline__ uint32_t smem_u32(const void* p) {
    uint32_t a;
    asm("{ .reg .u64 t; cvta.to.shared.u64 t, %1; cvt.u32.u64 %0, t; }" : "=r"(a) : "l"(p));
    return a;
}
#define CP_ASYNC16(dst, src) \
    asm volatile("cp.async.cg.shared.global [%0], [%1], 16;" :: "r"(dst), "l"(src))
#define CP_ASYNC16Z(dst, src, vbytes) \
    asm volatile("cp.async.cg.shared.global [%0], [%1], 16, %2;" :: "r"(dst), "l"(src), "r"(vbytes))
#define CP_COMMIT() asm volatile("cp.async.commit_group;" ::: "memory")
#define CP_WAIT(n)  asm volatile("cp.async.wait_group %0;" :: "n"(n) : "memory")

#define LDSM4(r, addr) \
    asm volatile("ldmatrix.sync.aligned.m8n8.x4.shared.b16 {%0,%1,%2,%3}, [%4];" \
        : "=r"((r)[0]), "=r"((r)[1]), "=r"((r)[2]), "=r"((r)[3]) : "r"(addr))
#define LDSM4T(r, addr) \
    asm volatile("ldmatrix.sync.aligned.m8n8.x4.trans.shared.b16 {%0,%1,%2,%3}, [%4];" \
        : "=r"((r)[0]), "=r"((r)[1]), "=r"((r)[2]), "=r"((r)[3]) : "r"(addr))

__device__ __forceinline__ void mma16816(float* c, const uint32_t* a, const uint32_t* b) {
    asm volatile("mma.sync.aligned.m16n8k16.row.col.f32.f16.f16.f32 "
        "{%0,%1,%2,%3}, {%4,%5,%6,%7}, {%8,%9}, {%0,%1,%2,%3};"
        : "+f"(c[0]), "+f"(c[1]), "+f"(c[2]), "+f"(c[3])
        : "r"(a[0]), "r"(a[1]), "r"(a[2]), "r"(a[3]), "r"(b[0]), "r"(b[1]));
}

__device__ __forceinline__ uint32_t pack2(float x, float y) {
    __half2 h; h.x = __float2half(x); h.y = __float2half(y);
    return *(uint32_t*)&h;
}
__device__ __forceinline__ uint32_t h2ex2(uint32_t x) {
    uint32_t r; asm("ex2.approx.f16x2 %0, %1;" : "=r"(r) : "r"(x)); return r;
}

// fast exact-GELU: erf via Abramowitz-Stegun 7.1.26 (|err| <= 1.5e-7)
__device__ __forceinline__ float gelu_fast(float x) {
    float ax = fabsf(x) * 0.70710678118654752f;
    float t = __frcp_rn(fmaf(0.3275911f, ax, 1.f));
    float poly = t * fmaf(t, fmaf(t, fmaf(t, fmaf(t, 1.061405429f, -1.453152027f),
                       1.421413741f), -0.284496736f), 0.254829592f);
    float er = 1.f - poly * __expf(-ax * ax);
    er = (x < 0.f) ? -er : er;
    return 0.5f * x * (1.f + er);
}

// Q prescale: log2(e) / sqrt(hd)  (scores land in log2 domain for ex2)
#define QSCALE (1.4426950408889634f / 5.656854249492380f)

// ---------------- fused: counts/starts (block 0) + weight converts ----------
#define NW0 (3 * H * H)
#define NW1 (H * H)
#define NW2 (4 * H * H)
#define NW3 (4 * H * H)
#define NWT (NW0 + NW1 + NW2 + NW3)
__global__ void prep_kernel(const int* __restrict__ batch,
                            const float* __restrict__ s0, const float* __restrict__ s1,
                            const float* __restrict__ s2, const float* __restrict__ s3,
                            __half* __restrict__ d0, __half* __restrict__ d1,
                            __half* __restrict__ d2, __half* __restrict__ d3)
{
    if (blockIdx.x == 0) {
        __shared__ int s[BG];
        int t = threadIdx.x;
        if (t < BG) s[t] = 0;
        __syncthreads();
        for (int i = t; i < NN; i += blockDim.x) atomicAdd(&s[batch[i]], 1);
        __syncthreads();
        if (t == 0) {
            int acc = 0;
            for (int b = 0; b < BG; b++) { g_starts[b] = acc; g_counts[b] = s[b]; acc += s[b]; }
        }
        return;
    }
    int i = (blockIdx.x - 1) * blockDim.x + threadIdx.x;
    if (i < NW0)                          d0[i] = __float2half(s0[i]);
    else if (i < NW0 + NW1)               d1[i - NW0] = __float2half(s1[i - NW0]);
    else if (i < NW0 + NW1 + NW2)         d2[i - NW0 - NW1] = __float2half(s2[i - NW0 - NW1]);
    else if (i < NWT)                     d3[i - NW0 - NW1 - NW2] = __float2half(s3[i - NW0 - NW1 - NW2]);
}

// ---------------- GraphNorm (8-way row-parallel) ----------------------------
__global__ void graphnorm_kernel(const float* __restrict__ in,
                                 const float* __restrict__ w,
                                 const float* __restrict__ bias,
                                 __half* __restrict__ oh)
{
    int b = blockIdx.x;
    int c = g_counts[b];
    long s = g_starts[b];
    if (c == 0) return;
    int t = threadIdx.x;
    int f = blockIdx.y * 32 + (t & 31);
    int rl = t >> 5;

    __shared__ float ssum[8][33], ssq[8][33], smean[32], sinv[32];

    float sum = 0.f, sq = 0.f;
    for (int i = rl; i < c; i += 8) {
        float v = in[(s + i) * H + f];
        sum += v; sq += v * v;
    }
    ssum[rl][t & 31] = sum; ssq[rl][t & 31] = sq;
    __syncthreads();
    if (rl == 0) {
        float ts = 0.f, tq = 0.f;
        #pragma unroll
        for (int k = 0; k < 8; k++) { ts += ssum[k][t & 31]; tq += ssq[k][t & 31]; }
        float cf = (float)c;
        float mean = ts / cf;
        float var = fmaxf((tq - ts * ts / cf) / fmaxf(cf - 1.f, 1.f), 0.f);
        smean[t & 31] = mean;
        sinv[t & 31] = 1.f / (sqrtf(var) + 1e-5f);
    }
    __syncthreads();
    float mean = smean[t & 31], inv = sinv[t & 31];
    float ww = w[f], bb = bias[f];
    for (int i = rl; i < c; i += 8)
        oh[(s + i) * H + f] = __float2half(ww * ((in[(s + i) * H + f] - mean) * inv) + bb);
}

// ======== HMMA GEMM (fp16, 128x128 tile, paired 64-K epochs, 2 CTA/SM) ======
#define SROW   80
#define ARR_SZ (128 * SROW)        // 10240
#define STG_SZ (2 * ARR_SZ)        // 20480
#define GEMM_SMEM (4 * STG_SZ)     // 81920  (x2 CTA = 163840 <= 228KB)

// EPI 1: bias+res->f32   2: gelu(bias)->fp16   3: bias->fp16, Q cols pre-scaled
template<int EPI>
__global__ __launch_bounds__(256, 2) void hgemm_kernel(
    const __half* __restrict__ Ah, const __half* __restrict__ Bh,
    const float* __restrict__ bias, const float* __restrict__ res,
    float* __restrict__ Cf, __half* __restrict__ Ch,
    int Nc, int K)
{
    extern __shared__ char sm[];
    const int tid  = threadIdx.x;
    const int wid  = tid >> 5, lane = tid & 31;
    const int quad = lane >> 2, pair = lane & 3;
    const int m0 = blockIdx.y << 7, n0 = blockIdx.x << 7;
    const int wm = (wid & 1) << 6;
    const int wn = (wid >> 1) << 5;
    const uint32_t smb = smem_u32(sm);

    const int offA = ((lane & 7) + ((lane >> 3) & 1) * 8) * SROW + ((lane >> 4) & 1) * 16;
    const int offB = (((lane >> 4) & 1) * 8 + (lane & 7)) * SROW + ((lane >> 3) & 1) * 16;

    float acc[4][4][4];
    #pragma unroll
    for (int a = 0; a < 4; a++)
        #pragma unroll
        for (int b = 0; b < 4; b++)
            #pragma unroll
            for (int r = 0; r < 4; r++) acc[a][b][r] = 0.f;

    const int nep = K >> 6;

    auto load_pair = [&](int e) {
        int k0 = e << 6;
        uint32_t sb = smb + ((2 * e) & 3) * STG_SZ;
        #pragma unroll
        for (int half = 0; half < 2; half++) {
            uint32_t hb = sb + half * STG_SZ;
            #pragma unroll
            for (int t = 0; t < 4; t++) {
                int task = tid + (t << 8);
                int arr  = task >> 9;
                int idx  = task & 511;
                int row  = idx >> 2, ch = idx & 3;
                int r0   = arr ? n0 : m0;
                const char* src = (const char*)(arr ? Bh : Ah)
                    + ((size_t)(r0 + row) * K + k0 + half * 32 + ch * 8) * 2;
                uint32_t dst = hb + arr * ARR_SZ + row * SROW + ch * 16;
                CP_ASYNC16(dst, src);
            }
        }
        CP_COMMIT();
    };

    load_pair(0);
    for (int e = 0; e < nep; e++) {
        CP_WAIT(0);
        __syncthreads();
        if (e + 1 < nep) load_pair(e + 1);

        #pragma unroll
        for (int half = 0; half < 2; half++) {
            const int stg = (((2 * e) & 3) + half) * STG_SZ;
            #pragma unroll
            for (int ks = 0; ks < 2; ks++) {
                const int kb = ks * 32;
                uint32_t afh[4][4], bfh[2][4];
                #pragma unroll
                for (int mt = 0; mt < 4; mt++)
                    LDSM4(afh[mt], smb + stg + (wm + mt * 16) * SROW + kb + offA);
                #pragma unroll
                for (int jp = 0; jp < 2; jp++)
                    LDSM4(bfh[jp], smb + stg + ARR_SZ + (wn + jp * 16) * SROW + kb + offB);
                #pragma unroll
                for (int mt = 0; mt < 4; mt++)
                    #pragma unroll
                    for (int nt = 0; nt < 4; nt++)
                        mma16816(acc[mt][nt], afh[mt], &bfh[nt >> 1][(nt & 1) * 2]);
            }
        }
    }

    // ---- epilogue ----
    #pragma unroll
    for (int mt = 0; mt < 4; mt++) {
        int row0 = m0 + wm + mt * 16 + quad;
        int row1 = row0 + 8;
        #pragma unroll
        for (int nt = 0; nt < 4; nt++) {
            int col = n0 + wn + nt * 8 + pair * 2;
            float b0v = bias[col], b1v = bias[col + 1];
            float v00 = acc[mt][nt][0] + b0v, v01 = acc[mt][nt][1] + b1v;
            float v10 = acc[mt][nt][2] + b0v, v11 = acc[mt][nt][3] + b1v;
            if (EPI == 2) {
                v00 = gelu_fast(v00);
                v01 = gelu_fast(v01);
                v10 = gelu_fast(v10);
                v11 = gelu_fast(v11);
            }
            if (EPI == 3 && col < H) {
                v00 *= QSCALE; v01 *= QSCALE; v10 *= QSCALE; v11 *= QSCALE;
            }
            if (EPI == 2 || EPI == 3) {
                *(uint32_t*)&Ch[(size_t)row0 * Nc + col] = pack2(v00, v01);
                *(uint32_t*)&Ch[(size_t)row1 * Nc + col] = pack2(v10, v11);
            } else {
                v00 += res[(size_t)row0 * Nc + col];
                v01 += res[(size_t)row0 * Nc + col + 1];
                v10 += res[(size_t)row1 * Nc + col];
                v11 += res[(size_t)row1 * Nc + col + 1];
                *(float2*)(Cf + (size_t)row0 * Nc + col) = make_float2(v00, v01);
                *(float2*)(Cf + (size_t)row1 * Nc + col) = make_float2(v10, v11);
            }
        }
    }
}

// ====== tensor-core flash attention (fp16, log2 softmax, 128-key chunks) ====
// KV loaded in 128-row chunks (one issue+wait+sync per 128 keys), computed as
// two 64-col halves with the same register footprint.  Row sums by MMA against
// a constant all-ones B fragment; P = ex2.approx.f16x2.
#define AQH   0                     // Q tile: 128 rows x 80B = 10240
#define AKV   10240                 // buf b at AKV + b*20480: [K 10240][V 10240]
#define KVB   20480
#define ATT_SMEM (AQH + 10240 + 2 * KVB)   // 51200  (x3 CTA = 153.6KB)

__global__ __launch_bounds__(256) void attn_kernel(
    const __half* __restrict__ qkv, __half* __restrict__ ctx)
{
    int b  = blockIdx.z, h = blockIdx.y, qt = blockIdx.x;
    int cc = g_counts[b];
    int s  = g_starts[b];
    int q0 = qt << 7;
    if (q0 >= cc) return;

    __shared__ alignas(128) char sm[ATT_SMEM];
    const uint32_t smb = smem_u32(sm);
    const int tid = threadIdx.x, w = tid >> 5, l = tid & 31;

    const int offA = ((l & 7) + ((l >> 3) & 1) * 8) * SROW + ((l >> 4) & 1) * 16;
    const int offB = (((l >> 4) & 1) * 8 + (l & 7)) * SROW + ((l >> 3) & 1) * 16;

    // ---- Q tile (128 x 32) ----
    {
        #pragma unroll
        for (int t = 0; t < 2; t++) {
            int idx = tid + (t << 8);
            int row = idx >> 2, seg = idx & 3;
            const __half* src = qkv + (size_t)(s + q0 + row) * (3 * H) + h * HD + seg * 8;
            uint32_t dst = smb + row * SROW + seg * 16;
            CP_ASYNC16Z(dst, src, (q0 + row < cc) ? 16u : 0u);
        }
        CP_COMMIT();
    }
    // issue one 128-row KV chunk (K + V), zero-filling rows beyond cc
    auto issue_kv = [&](int k0, int buf) {
        #pragma unroll
        for (int t = 0; t < 4; t++) {
            int task = tid + (t << 8);               // 0..1023
            int arr = task >> 9, idx = task & 511;   // 0 K, 1 V
            int row = idx >> 2, seg = idx & 3;
            const __half* src = qkv + (size_t)(s + k0 + row) * (3 * H) + h * HD + (arr + 1) * H + seg * 8;
            uint32_t dst = smb + AKV + buf * KVB + arr * 10240 + row * SROW + seg * 16;
            CP_ASYNC16Z(dst, src, (k0 + row < cc) ? 16u : 0u);
        }
        CP_COMMIT();
    };
    issue_kv(0, 0);
    CP_WAIT(0);
    __syncthreads();

    uint32_t qf[2][4];
    #pragma unroll
    for (int kc = 0; kc < 2; kc++)
        LDSM4(qf[kc], smb + (w * 16) * SROW + kc * 32 + offA);

    const uint32_t ONE2 = 0x3C003C00u;
    uint32_t ones_b[2] = { ONE2, ONE2 };

    float osum[4] = {0.f, 0.f, 0.f, 0.f};
    float o[4][4];
    #pragma unroll
    for (int dt = 0; dt < 4; dt++)
        #pragma unroll
        for (int r = 0; r < 4; r++) o[dt][r] = 0.f;

    int nch = (cc - 1) / 128 + 1;
    for (int ci = 0; ci < nch; ci++) {
        int k0 = ci * 128;
        uint32_t kvb = smb + AKV + (ci & 1) * KVB;
        if (ci + 1 < nch) issue_kv(k0 + 128, (ci + 1) & 1);

        #pragma unroll
        for (int half = 0; half < 2; half++) {
            int kh0 = k0 + half * 64;
            if (kh0 >= cc) break;
            uint32_t kbase = kvb + half * 64 * SROW;           // K rows
            uint32_t vbase = kvb + 10240 + half * 64 * SROW;   // V rows

            // ---- S = Q K^T (log2 domain) ----
            float sc[8][4];
            #pragma unroll
            for (int j = 0; j < 8; j++)
                #pragma unroll
                for (int r = 0; r < 4; r++) sc[j][r] = 0.f;

            #pragma unroll
            for (int jp = 0; jp < 4; jp++) {
                #pragma unroll
                for (int kc = 0; kc < 2; kc++) {
                    uint32_t kh[4];
                    LDSM4(kh, kbase + (jp * 16) * SROW + kc * 32 + offB);
                    mma16816(sc[2 * jp],     qf[kc], kh);
                    mma16816(sc[2 * jp + 1], qf[kc], kh + 2);
                }
            }
            // ---- mask only the straddling half ----
            if (kh0 + 64 > cc) {
                int colb = kh0 + 2 * (l & 3);
                #pragma unroll
                for (int j = 0; j < 8; j++) {
                    int c0 = colb + j * 8, c1 = c0 + 1;
                    if (c0 >= cc) { sc[j][0] = -1e9f; sc[j][2] = -1e9f; }
                    if (c1 >= cc) { sc[j][1] = -1e9f; sc[j][3] = -1e9f; }
                }
            }
            // ---- P = ex2(s) packed fp16 ----
            uint32_t pa[4][4];
            #pragma unroll
            for (int kc = 0; kc < 4; kc++) {
                int j = 2 * kc;
                pa[kc][0] = h2ex2(pack2(sc[j][0], sc[j][1]));
                pa[kc][1] = h2ex2(pack2(sc[j][2], sc[j][3]));
                pa[kc][2] = h2ex2(pack2(sc[j + 1][0], sc[j + 1][1]));
                pa[kc][3] = h2ex2(pack2(sc[j + 1][2], sc[j + 1][3]));
            }
            // ---- O += P V ;  osum += P 1 ----
            #pragma unroll
            for (int kc = 0; kc < 4; kc++) {
                uint32_t vhA[4], vhB[4];
                uint32_t a = vbase + (kc * 16) * SROW + offA;
                LDSM4T(vhA, a);
                LDSM4T(vhB, a + 32);
                mma16816(o[0], pa[kc], vhA);
                mma16816(o[1], pa[kc], vhA + 2);
                mma16816(o[2], pa[kc], vhB);
                mma16816(o[3], pa[kc], vhB + 2);
                mma16816(osum, pa[kc], ones_b);
            }
        }
        if (ci + 1 < nch) CP_WAIT(0);
        __syncthreads();
    }

    float inv0 = 1.f / osum[0];     // row r0 denominator
    float inv1 = 1.f / osum[2];     // row r1 denominator
    int r0 = q0 + w * 16 + (l >> 2);
    int r1 = r0 + 8;
    #pragma unroll
    for (int dt = 0; dt < 4; dt++) {
        int d = h * HD + dt * 8 + 2 * (l & 3);
        if (r0 < cc)
            *(uint32_t*)&ctx[(size_t)(s + r0) * H + d] = pack2(o[dt][0] * inv0, o[dt][1] * inv0);
        if (r1 < cc)
            *(uint32_t*)&ctx[(size_t)(s + r1) * H + d] = pack2(o[dt][2] * inv1, o[dt][3] * inv1);
    }
}

// ======================= launch =============================================
extern "C" void kernel_launch(void* const* d_in, const int* in_sizes, int n_in,
                              void* d_out, int out_size)
{
    const float* x     = (const float*)d_in[0];
    const int*   batch = (const int*)d_in[1];
    int base = (n_in >= 15 && in_sizes[2] == 1) ? 3 : 2;
    const float* n1w = (const float*)d_in[base + 0];
    const float* n1b = (const float*)d_in[base + 1];
    const float* iw  = (const float*)d_in[base + 2];
    const float* ib  = (const float*)d_in[base + 3];
    const float* ow  = (const float*)d_in[base + 4];
    const float* ob  = (const float*)d_in[base + 5];
    const float* n2w = (const float*)d_in[base + 6];
    const float* n2b = (const float*)d_in[base + 7];
    const float* w1  = (const float*)d_in[base + 8];
    const float* b1  = (const float*)d_in[base + 9];
    const float* w2  = (const float*)d_in[base + 10];
    const float* b2  = (const float*)d_in[base + 11];
    float* out = (float*)d_out;

    cudaFuncSetAttribute(hgemm_kernel<1>, cudaFuncAttributeMaxDynamicSharedMemorySize, GEMM_SMEM);
    cudaFuncSetAttribute(hgemm_kernel<2>, cudaFuncAttributeMaxDynamicSharedMemorySize, GEMM_SMEM);
    cudaFuncSetAttribute(hgemm_kernel<3>, cudaFuncAttributeMaxDynamicSharedMemorySize, GEMM_SMEM);

    __half *p_xn, *p_qkv, *p_ctx, *p_xn2, *p_hid, *p_wq, *p_wo, *p_w1, *p_w2;
    float *p_xmid;
    cudaGetSymbolAddress((void**)&p_xn,   g_xn);
    cudaGetSymbolAddress((void**)&p_qkv,  g_qkv);
    cudaGetSymbolAddress((void**)&p_ctx,  g_ctx);
    cudaGetSymbolAddress((void**)&p_xmid, g_xmid);
    cudaGetSymbolAddress((void**)&p_xn2,  g_xn2);
    cudaGetSymbolAddress((void**)&p_hid,  g_hid);
    cudaGetSymbolAddress((void**)&p_wq,   g_wqkv);
    cudaGetSymbolAddress((void**)&p_wo,   g_wout);
    cudaGetSymbolAddress((void**)&p_w1,   g_w1);
    cudaGetSymbolAddress((void**)&p_w2,   g_w2);

    prep_kernel<<<1 + (NWT + 255) / 256, 256>>>(
        batch, iw, ow, w1, w2, p_wq, p_wo, p_w1, p_w2);
    graphnorm_kernel<<<dim3(BG, 8), 256>>>(x, n1w, n1b, p_xn);

    hgemm_kernel<3><<<dim3(3 * H / 128, NN / 128), 256, GEMM_SMEM>>>(
        p_xn, p_wq, ib, nullptr, nullptr, p_qkv, 3 * H, H);

    attn_kernel<<<dim3(4, NHEADS, BG), 256>>>(p_qkv, p_ctx);   // profiled slot

    hgemm_kernel<1><<<dim3(H / 128, NN / 128), 256, GEMM_SMEM>>>(
        p_ctx, p_wo, ob, x, p_xmid, nullptr, H, H);

    graphnorm_kernel<<<dim3(BG, 8), 256>>>(p_xmid, n2w, n2b, p_xn2);

    hgemm_kernel<2><<<dim3(4 * H / 128, NN / 128), 256, GEMM_SMEM>>>(
        p_xn2, p_w1, b1, nullptr, nullptr, p_hid, 4 * H, H);

    hgemm_kernel<1><<<dim3(H / 128, NN / 128), 256, GEMM_SMEM>>>(
        p_hid, p_w2, b2, p_xmid, out, nullptr, H, 4 * H);
}

// round 17
// speedup vs baseline: 1.0222x; 1.0222x over previous
#include <cuda_runtime.h>
#include <cuda_fp16.h>
#include <math.h>
#include <stdint.h>

#define NN      16384
#define BG      64
#define H       256
#define NHEADS  8
#define HD      32

// ======================= scratch (device globals) ===========================
__device__ __half g_xn [NN * H];
__device__ __half g_qkv[NN * 3 * H];
__device__ __half g_ctx[NN * H];
__device__ float  g_xmid[NN * H];
__device__ __half g_xn2[NN * H];
__device__ __half g_hid[NN * 4 * H];
__device__ __half g_wqkv[3 * H * H];
__device__ __half g_wout[H * H];
__device__ __half g_w1[4 * H * H];
__device__ __half g_w2[H * 4 * H];
__device__ int g_counts[BG];
__device__ int g_starts[BG];

__device__ __forceinline__ uint32_t smem_u32(const void* p) {
    uint32_t a;
    asm("{ .reg .u64 t; cvta.to.shared.u64 t, %1; cvt.u32.u64 %0, t; }" : "=r"(a) : "l"(p));
    return a;
}
#define CP_ASYNC16(dst, src) \
    asm volatile("cp.async.cg.shared.global [%0], [%1], 16;" :: "r"(dst), "l"(src))
#define CP_ASYNC16Z(dst, src, vbytes) \
    asm volatile("cp.async.cg.shared.global [%0], [%1], 16, %2;" :: "r"(dst), "l"(src), "r"(vbytes))
#define CP_COMMIT() asm volatile("cp.async.commit_group;" ::: "memory")
#define CP_WAIT(n)  asm volatile("cp.async.wait_group %0;" :: "n"(n) : "memory")

#define LDSM4(r, addr) \
    asm volatile("ldmatrix.sync.aligned.m8n8.x4.shared.b16 {%0,%1,%2,%3}, [%4];" \
        : "=r"((r)[0]), "=r"((r)[1]), "=r"((r)[2]), "=r"((r)[3]) : "r"(addr))
#define LDSM4T(r, addr) \
    asm volatile("ldmatrix.sync.aligned.m8n8.x4.trans.shared.b16 {%0,%1,%2,%3}, [%4];" \
        : "=r"((r)[0]), "=r"((r)[1]), "=r"((r)[2]), "=r"((r)[3]) : "r"(addr))

__device__ __forceinline__ void mma16816(float* c, const uint32_t* a, const uint32_t* b) {
    asm volatile("mma.sync.aligned.m16n8k16.row.col.f32.f16.f16.f32 "
        "{%0,%1,%2,%3}, {%4,%5,%6,%7}, {%8,%9}, {%0,%1,%2,%3};"
        : "+f"(c[0]), "+f"(c[1]), "+f"(c[2]), "+f"(c[3])
        : "r"(a[0]), "r"(a[1]), "r"(a[2]), "r"(a[3]), "r"(b[0]), "r"(b[1]));
}

__device__ __forceinline__ uint32_t pack2(float x, float y) {
    __half2 h; h.x = __float2half(x); h.y = __float2half(y);
    return *(uint32_t*)&h;
}
__device__ __forceinline__ uint32_t h2ex2(uint32_t x) {
    uint32_t r; asm("ex2.approx.f16x2 %0, %1;" : "=r"(r) : "r"(x)); return r;
}

// fast exact-GELU: erf via Abramowitz-Stegun 7.1.26 (|err| <= 1.5e-7)
__device__ __forceinline__ float gelu_fast(float x) {
    float ax = fabsf(x) * 0.70710678118654752f;
    float t = __frcp_rn(fmaf(0.3275911f, ax, 1.f));
    float poly = t * fmaf(t, fmaf(t, fmaf(t, fmaf(t, 1.061405429f, -1.453152027f),
                       1.421413741f), -0.284496736f), 0.254829592f);
    float er = 1.f - poly * __expf(-ax * ax);
    er = (x < 0.f) ? -er : er;
    return 0.5f * x * (1.f + er);
}

// Q prescale: log2(e) / sqrt(hd)  (scores land in log2 domain for ex2)
#define QSCALE (1.4426950408889634f / 5.656854249492380f)

// ---------------- fused: counts/starts (block 0) + weight converts ----------
#define NW0 (3 * H * H)
#define NW1 (H * H)
#define NW2 (4 * H * H)
#define NW3 (4 * H * H)
#define NWT (NW0 + NW1 + NW2 + NW3)
__global__ void prep_kernel(const int* __restrict__ batch,
                            const float* __restrict__ s0, const float* __restrict__ s1,
                            const float* __restrict__ s2, const float* __restrict__ s3,
                            __half* __restrict__ d0, __half* __restrict__ d1,
                            __half* __restrict__ d2, __half* __restrict__ d3)
{
    if (blockIdx.x == 0) {
        __shared__ int s[BG];
        int t = threadIdx.x;
        if (t < BG) s[t] = 0;
        __syncthreads();
        for (int i = t; i < NN; i += blockDim.x) atomicAdd(&s[batch[i]], 1);
        __syncthreads();
        if (t == 0) {
            int acc = 0;
            for (int b = 0; b < BG; b++) { g_starts[b] = acc; g_counts[b] = s[b]; acc += s[b]; }
        }
        return;
    }
    int i = (blockIdx.x - 1) * blockDim.x + threadIdx.x;
    if (i < NW0)                          d0[i] = __float2half(s0[i]);
    else if (i < NW0 + NW1)               d1[i - NW0] = __float2half(s1[i - NW0]);
    else if (i < NW0 + NW1 + NW2)         d2[i - NW0 - NW1] = __float2half(s2[i - NW0 - NW1]);
    else if (i < NWT)                     d3[i - NW0 - NW1 - NW2] = __float2half(s3[i - NW0 - NW1 - NW2]);
}

// ---------------- GraphNorm (16-way row-parallel, 512 threads) --------------
__global__ __launch_bounds__(512) void graphnorm_kernel(
    const float* __restrict__ in,
    const float* __restrict__ w,
    const float* __restrict__ bias,
    __half* __restrict__ oh)
{
    int b = blockIdx.x;
    int c = g_counts[b];
    long s = g_starts[b];
    if (c == 0) return;
    int t = threadIdx.x;
    int f = blockIdx.y * 32 + (t & 31);     // feature (32 per block)
    int rl = t >> 5;                        // 0..15 row lane

    __shared__ float ssum[16][33], ssq[16][33], smean[32], sinv[32];

    float sum = 0.f, sq = 0.f;
    for (int i = rl; i < c; i += 16) {
        float v = in[(s + i) * H + f];
        sum += v; sq += v * v;
    }
    ssum[rl][t & 31] = sum; ssq[rl][t & 31] = sq;
    __syncthreads();
    if (rl == 0) {
        float ts = 0.f, tq = 0.f;
        #pragma unroll
        for (int k = 0; k < 16; k++) { ts += ssum[k][t & 31]; tq += ssq[k][t & 31]; }
        float cf = (float)c;
        float mean = ts / cf;
        float var = fmaxf((tq - ts * ts / cf) / fmaxf(cf - 1.f, 1.f), 0.f);
        smean[t & 31] = mean;
        sinv[t & 31] = 1.f / (sqrtf(var) + 1e-5f);
    }
    __syncthreads();
    // normalize pass: each thread handles a feature PAIR (2-way vector store)
    int f2 = blockIdx.y * 32 + 2 * (t & 15);   // 16 pairs per block
    int rl2 = t >> 4;                          // 0..31 row lane
    float m0v = smean[2 * (t & 15)],     i0v = sinv[2 * (t & 15)];
    float m1v = smean[2 * (t & 15) + 1], i1v = sinv[2 * (t & 15) + 1];
    float w0v = w[f2],     b0v = bias[f2];
    float w1v = w[f2 + 1], b1v = bias[f2 + 1];
    for (int i = rl2; i < c; i += 32) {
        float2 v = *(const float2*)&in[(s + i) * H + f2];
        float y0 = w0v * ((v.x - m0v) * i0v) + b0v;
        float y1 = w1v * ((v.y - m1v) * i1v) + b1v;
        *(uint32_t*)&oh[(s + i) * H + f2] = pack2(y0, y1);
    }
}

// ======== HMMA GEMM (fp16, 128x128 tile, paired 64-K epochs, 2 CTA/SM) ======
#define SROW   80
#define ARR_SZ (128 * SROW)        // 10240
#define STG_SZ (2 * ARR_SZ)        // 20480
#define GEMM_SMEM (4 * STG_SZ)     // 81920  (x2 CTA = 163840 <= 228KB)

// EPI 1: bias+res->f32   2: gelu(bias)->fp16   3: bias->fp16, Q cols pre-scaled
template<int EPI>
__global__ __launch_bounds__(256, 2) void hgemm_kernel(
    const __half* __restrict__ Ah, const __half* __restrict__ Bh,
    const float* __restrict__ bias, const float* __restrict__ res,
    float* __restrict__ Cf, __half* __restrict__ Ch,
    int Nc, int K)
{
    extern __shared__ char sm[];
    const int tid  = threadIdx.x;
    const int wid  = tid >> 5, lane = tid & 31;
    const int quad = lane >> 2, pair = lane & 3;
    const int m0 = blockIdx.y << 7, n0 = blockIdx.x << 7;
    const int wm = (wid & 1) << 6;
    const int wn = (wid >> 1) << 5;
    const uint32_t smb = smem_u32(sm);

    const int offA = ((lane & 7) + ((lane >> 3) & 1) * 8) * SROW + ((lane >> 4) & 1) * 16;
    const int offB = (((lane >> 4) & 1) * 8 + (lane & 7)) * SROW + ((lane >> 3) & 1) * 16;

    float acc[4][4][4];
    #pragma unroll
    for (int a = 0; a < 4; a++)
        #pragma unroll
        for (int b = 0; b < 4; b++)
            #pragma unroll
            for (int r = 0; r < 4; r++) acc[a][b][r] = 0.f;

    const int nep = K >> 6;

    auto load_pair = [&](int e) {
        int k0 = e << 6;
        uint32_t sb = smb + ((2 * e) & 3) * STG_SZ;
        #pragma unroll
        for (int half = 0; half < 2; half++) {
            uint32_t hb = sb + half * STG_SZ;
            #pragma unroll
            for (int t = 0; t < 4; t++) {
                int task = tid + (t << 8);
                int arr  = task >> 9;
                int idx  = task & 511;
                int row  = idx >> 2, ch = idx & 3;
                int r0   = arr ? n0 : m0;
                const char* src = (const char*)(arr ? Bh : Ah)
                    + ((size_t)(r0 + row) * K + k0 + half * 32 + ch * 8) * 2;
                uint32_t dst = hb + arr * ARR_SZ + row * SROW + ch * 16;
                CP_ASYNC16(dst, src);
            }
        }
        CP_COMMIT();
    };

    load_pair(0);
    for (int e = 0; e < nep; e++) {
        CP_WAIT(0);
        __syncthreads();
        if (e + 1 < nep) load_pair(e + 1);

        #pragma unroll
        for (int half = 0; half < 2; half++) {
            const int stg = (((2 * e) & 3) + half) * STG_SZ;
            #pragma unroll
            for (int ks = 0; ks < 2; ks++) {
                const int kb = ks * 32;
                uint32_t afh[4][4], bfh[2][4];
                #pragma unroll
                for (int mt = 0; mt < 4; mt++)
                    LDSM4(afh[mt], smb + stg + (wm + mt * 16) * SROW + kb + offA);
                #pragma unroll
                for (int jp = 0; jp < 2; jp++)
                    LDSM4(bfh[jp], smb + stg + ARR_SZ + (wn + jp * 16) * SROW + kb + offB);
                #pragma unroll
                for (int mt = 0; mt < 4; mt++)
                    #pragma unroll
                    for (int nt = 0; nt < 4; nt++)
                        mma16816(acc[mt][nt], afh[mt], &bfh[nt >> 1][(nt & 1) * 2]);
            }
        }
    }

    // ---- epilogue ----
    #pragma unroll
    for (int mt = 0; mt < 4; mt++) {
        int row0 = m0 + wm + mt * 16 + quad;
        int row1 = row0 + 8;
        #pragma unroll
        for (int nt = 0; nt < 4; nt++) {
            int col = n0 + wn + nt * 8 + pair * 2;
            float b0v = bias[col], b1v = bias[col + 1];
            float v00 = acc[mt][nt][0] + b0v, v01 = acc[mt][nt][1] + b1v;
            float v10 = acc[mt][nt][2] + b0v, v11 = acc[mt][nt][3] + b1v;
            if (EPI == 2) {
                v00 = gelu_fast(v00);
                v01 = gelu_fast(v01);
                v10 = gelu_fast(v10);
                v11 = gelu_fast(v11);
            }
            if (EPI == 3 && col < H) {
                v00 *= QSCALE; v01 *= QSCALE; v10 *= QSCALE; v11 *= QSCALE;
            }
            if (EPI == 2 || EPI == 3) {
                *(uint32_t*)&Ch[(size_t)row0 * Nc + col] = pack2(v00, v01);
                *(uint32_t*)&Ch[(size_t)row1 * Nc + col] = pack2(v10, v11);
            } else {
                v00 += res[(size_t)row0 * Nc + col];
                v01 += res[(size_t)row0 * Nc + col + 1];
                v10 += res[(size_t)row1 * Nc + col];
                v11 += res[(size_t)row1 * Nc + col + 1];
                *(float2*)(Cf + (size_t)row0 * Nc + col) = make_float2(v00, v01);
                *(float2*)(Cf + (size_t)row1 * Nc + col) = make_float2(v10, v11);
            }
        }
    }
}

// ============ tensor-core flash attention (fp16, log2-domain softmax) =======
// P = ex2(pack2(s)) via ex2.approx.f16x2; row sums via an extra MMA against a
// constant all-ones B fragment -> exact fp32 per-row denominators.
#define AQH 0                  // Q tile: 128 rows x 80B = 10240
#define AKV 10240              // buf b at AKV + b*10240: [KH 5120][VH 5120]
#define ATT_SMEM 30720

__global__ __launch_bounds__(256) void attn_kernel(
    const __half* __restrict__ qkv, __half* __restrict__ ctx)
{
    int b  = blockIdx.z, h = blockIdx.y, qt = blockIdx.x;
    int cc = g_counts[b];
    int s  = g_starts[b];
    int q0 = qt << 7;
    if (q0 >= cc) return;

    __shared__ alignas(128) char sm[ATT_SMEM];
    const uint32_t smb = smem_u32(sm);
    const int tid = threadIdx.x, w = tid >> 5, l = tid & 31;

    const int offA = ((l & 7) + ((l >> 3) & 1) * 8) * SROW + ((l >> 4) & 1) * 16;
    const int offB = (((l >> 4) & 1) * 8 + (l & 7)) * SROW + ((l >> 3) & 1) * 16;

    // ---- Q tile (128 x 32) ----
    {
        #pragma unroll
        for (int t = 0; t < 2; t++) {
            int idx = tid + (t << 8);
            int row = idx >> 2, seg = idx & 3;
            const __half* src = qkv + (size_t)(s + q0 + row) * (3 * H) + h * HD + seg * 8;
            uint32_t dst = smb + row * SROW + seg * 16;
            CP_ASYNC16Z(dst, src, (q0 + row < cc) ? 16u : 0u);
        }
        CP_COMMIT();
    }
    auto issue_kv = [&](int k0, int buf) {
        #pragma unroll
        for (int t = 0; t < 2; t++) {
            int task = tid + (t << 8);
            int arr = task >> 8, idx = task & 255;
            int row = idx >> 2, seg = idx & 3;
            const __half* src = qkv + (size_t)(s + k0 + row) * (3 * H) + h * HD + (arr + 1) * H + seg * 8;
            uint32_t dst = smb + AKV + buf * 10240 + arr * 5120 + row * SROW + seg * 16;
            CP_ASYNC16Z(dst, src, (k0 + row < cc) ? 16u : 0u);
        }
        CP_COMMIT();
    };
    issue_kv(0, 0);
    CP_WAIT(0);
    __syncthreads();

    uint32_t qf[2][4];
    #pragma unroll
    for (int kc = 0; kc < 2; kc++)
        LDSM4(qf[kc], smb + (w * 16) * SROW + kc * 32 + offA);

    const uint32_t ONE2 = 0x3C003C00u;
    uint32_t ones_b[2] = { ONE2, ONE2 };

    float osum[4] = {0.f, 0.f, 0.f, 0.f};
    float o[4][4];
    #pragma unroll
    for (int dt = 0; dt < 4; dt++)
        #pragma unroll
        for (int r = 0; r < 4; r++) o[dt][r] = 0.f;

    int nch = (cc - 1) / 64 + 1;
    for (int ci = 0; ci < nch; ci++) {
        int k0 = ci * 64;
        uint32_t kvb = smb + AKV + (ci & 1) * 10240;
        if (ci + 1 < nch) issue_kv(k0 + 64, (ci + 1) & 1);

        // ---- S = Q K^T (log2 domain, Q pre-scaled by log2e/sqrt(hd)) ----
        float sc[8][4];
        #pragma unroll
        for (int j = 0; j < 8; j++)
            #pragma unroll
            for (int r = 0; r < 4; r++) sc[j][r] = 0.f;

        #pragma unroll
        for (int jp = 0; jp < 4; jp++) {
            #pragma unroll
            for (int kc = 0; kc < 2; kc++) {
                uint32_t kh[4];
                LDSM4(kh, kvb + (jp * 16) * SROW + kc * 32 + offB);
                mma16816(sc[2 * jp],     qf[kc], kh);
                mma16816(sc[2 * jp + 1], qf[kc], kh + 2);
            }
        }
        // ---- mask only the final partial chunk ----
        if (k0 + 64 > cc) {
            int colb = k0 + 2 * (l & 3);
            #pragma unroll
            for (int j = 0; j < 8; j++) {
                int c0 = colb + j * 8, c1 = c0 + 1;
                if (c0 >= cc) { sc[j][0] = -1e9f; sc[j][2] = -1e9f; }
                if (c1 >= cc) { sc[j][1] = -1e9f; sc[j][3] = -1e9f; }
            }
        }
        // ---- P = ex2(s) packed fp16 ----
        uint32_t pa[4][4];
        #pragma unroll
        for (int kc = 0; kc < 4; kc++) {
            int j = 2 * kc;
            pa[kc][0] = h2ex2(pack2(sc[j][0], sc[j][1]));
            pa[kc][1] = h2ex2(pack2(sc[j][2], sc[j][3]));
            pa[kc][2] = h2ex2(pack2(sc[j + 1][0], sc[j + 1][1]));
            pa[kc][3] = h2ex2(pack2(sc[j + 1][2], sc[j + 1][3]));
        }
        // ---- O += P V ;  osum += P 1 ----
        #pragma unroll
        for (int kc = 0; kc < 4; kc++) {
            uint32_t vhA[4], vhB[4];
            uint32_t a = kvb + 5120 + (kc * 16) * SROW + offA;
            LDSM4T(vhA, a);
            LDSM4T(vhB, a + 32);
            mma16816(o[0], pa[kc], vhA);
            mma16816(o[1], pa[kc], vhA + 2);
            mma16816(o[2], pa[kc], vhB);
            mma16816(o[3], pa[kc], vhB + 2);
            mma16816(osum, pa[kc], ones_b);
        }
        if (ci + 1 < nch) CP_WAIT(0);
        __syncthreads();
    }

    float inv0 = 1.f / osum[0];
    float inv1 = 1.f / osum[2];
    int r0 = q0 + w * 16 + (l >> 2);
    int r1 = r0 + 8;
    #pragma unroll
    for (int dt = 0; dt < 4; dt++) {
        int d = h * HD + dt * 8 + 2 * (l & 3);
        if (r0 < cc)
            *(uint32_t*)&ctx[(size_t)(s + r0) * H + d] = pack2(o[dt][0] * inv0, o[dt][1] * inv0);
        if (r1 < cc)
            *(uint32_t*)&ctx[(size_t)(s + r1) * H + d] = pack2(o[dt][2] * inv1, o[dt][3] * inv1);
    }
}

// ======================= launch =============================================
extern "C" void kernel_launch(void* const* d_in, const int* in_sizes, int n_in,
                              void* d_out, int out_size)
{
    const float* x     = (const float*)d_in[0];
    const int*   batch = (const int*)d_in[1];
    int base = (n_in >= 15 && in_sizes[2] == 1) ? 3 : 2;
    const float* n1w = (const float*)d_in[base + 0];
    const float* n1b = (const float*)d_in[base + 1];
    const float* iw  = (const float*)d_in[base + 2];
    const float* ib  = (const float*)d_in[base + 3];
    const float* ow  = (const float*)d_in[base + 4];
    const float* ob  = (const float*)d_in[base + 5];
    const float* n2w = (const float*)d_in[base + 6];
    const float* n2b = (const float*)d_in[base + 7];
    const float* w1  = (const float*)d_in[base + 8];
    const float* b1  = (const float*)d_in[base + 9];
    const float* w2  = (const float*)d_in[base + 10];
    const float* b2  = (const float*)d_in[base + 11];
    float* out = (float*)d_out;

    cudaFuncSetAttribute(hgemm_kernel<1>, cudaFuncAttributeMaxDynamicSharedMemorySize, GEMM_SMEM);
    cudaFuncSetAttribute(hgemm_kernel<2>, cudaFuncAttributeMaxDynamicSharedMemorySize, GEMM_SMEM);
    cudaFuncSetAttribute(hgemm_kernel<3>, cudaFuncAttributeMaxDynamicSharedMemorySize, GEMM_SMEM);

    __half *p_xn, *p_qkv, *p_ctx, *p_xn2, *p_hid, *p_wq, *p_wo, *p_w1, *p_w2;
    float *p_xmid;
    cudaGetSymbolAddress((void**)&p_xn,   g_xn);
    cudaGetSymbolAddress((void**)&p_qkv,  g_qkv);
    cudaGetSymbolAddress((void**)&p_ctx,  g_ctx);
    cudaGetSymbolAddress((void**)&p_xmid, g_xmid);
    cudaGetSymbolAddress((void**)&p_xn2,  g_xn2);
    cudaGetSymbolAddress((void**)&p_hid,  g_hid);
    cudaGetSymbolAddress((void**)&p_wq,   g_wqkv);
    cudaGetSymbolAddress((void**)&p_wo,   g_wout);
    cudaGetSymbolAddress((void**)&p_w1,   g_w1);
    cudaGetSymbolAddress((void**)&p_w2,   g_w2);

    prep_kernel<<<1 + (NWT + 255) / 256, 256>>>(
        batch, iw, ow, w1, w2, p_wq, p_wo, p_w1, p_w2);
    graphnorm_kernel<<<dim3(BG, 8), 512>>>(x, n1w, n1b, p_xn);

    hgemm_kernel<3><<<dim3(3 * H / 128, NN / 128), 256, GEMM_SMEM>>>(
        p_xn, p_wq, ib, nullptr, nullptr, p_qkv, 3 * H, H);

    attn_kernel<<<dim3(4, NHEADS, BG), 256>>>(p_qkv, p_ctx);   // profiled slot

    hgemm_kernel<1><<<dim3(H / 128, NN / 128), 256, GEMM_SMEM>>>(
        p_ctx, p_wo, ob, x, p_xmid, nullptr, H, H);

    graphnorm_kernel<<<dim3(BG, 8), 512>>>(p_xmid, n2w, n2b, p_xn2);

    hgemm_kernel<2><<<dim3(4 * H / 128, NN / 128), 256, GEMM_SMEM>>>(
        p_xn2, p_w1, b1, nullptr, nullptr, p_hid, 4 * H, H);

    hgemm_kernel<1><<<dim3(H / 128, NN / 128), 256, GEMM_SMEM>>>(
        p_hid, p_w2, b2, p_xmid, out, nullptr, H, 4 * H);
}